// round 13
// baseline (speedup 1.0000x reference)
#include <cuda_runtime.h>
#include <cstdint>

// Problem dims (fixed)
#define B_ 128
#define C_ 16
#define F_ 128
#define D_ 512

// ---------------- global scratch (no allocation allowed) -------------------
// A (normalized c_feats) split tf32 hi/lo, per-row permuted into HMMA frag
// order: idx(m,k) = m*512 + (k>>3)*8 + (k&3)*2 + ((k>>2)&1)
__device__ float g_Ahi[2048 * 512];
__device__ float g_Alo[2048 * 512];
// B (f_feats) split tf32 hi/lo, per-n frag order:
// idx(n,k,f) = n*65536 + (k>>3)*1024 + (k&3)*256 + f*2 + ((k>>2)&1)
__device__ float g_Bhi[128 * 65536];
__device__ float g_Blo[128 * 65536];
__device__ float g_rnc[2048];              // 1/||c_feats row||
__device__ float g_rnf[128 * 128];         // 1/||f_feats[n,f]||

__device__ __forceinline__ float to_tf32(float x) {
    uint32_t u; asm("cvt.rna.tf32.f32 %0, %1;" : "=r"(u) : "f"(x));
    return __uint_as_float(u);
}

// ---------------------------------------------------------------------------
// Kernel A: reciprocal row norms for both tensors.
// ---------------------------------------------------------------------------
__global__ void prep_norms(const float* __restrict__ cf, const float* __restrict__ ff) {
    int row = blockIdx.x;
    int t = threadIdx.x;  // 128 threads, one float4 each
    const float* src = (row < 2048) ? (cf + (size_t)row * D_)
                                    : (ff + (size_t)(row - 2048) * D_);
    float4 v = ((const float4*)src)[t];
    float ss = v.x * v.x + v.y * v.y + v.z * v.z + v.w * v.w;
#pragma unroll
    for (int o = 16; o > 0; o >>= 1) ss += __shfl_xor_sync(0xffffffffu, ss, o);
    __shared__ float sred[4];
    if ((t & 31) == 0) sred[t >> 5] = ss;
    __syncthreads();
    if (t == 0) {
        float nrm = sqrtf(sred[0] + sred[1] + sred[2] + sred[3]);
        if (row < 2048) g_rnc[row] = 1.0f / nrm;
        else            g_rnf[row - 2048] = 1.0f / nrm;
    }
}

// ---------------------------------------------------------------------------
// Kernel A2: normalize + tf32-split c_feats into frag-ordered g_Ahi/g_Alo.
// grid 2048, 128 threads (4 k per thread).
// ---------------------------------------------------------------------------
__global__ void split_a(const float* __restrict__ cf) {
    int m = blockIdx.x, t = threadIdx.x;
    float rn = g_rnc[m];
    float4 v = ((const float4*)(cf + (size_t)m * D_))[t];
    float vals[4] = {v.x * rn, v.y * rn, v.z * rn, v.w * rn};
    size_t base = (size_t)m * 512;
#pragma unroll
    for (int j = 0; j < 4; j++) {
        int k = t * 4 + j;
        float hi = to_tf32(vals[j]);
        float lo = to_tf32(vals[j] - hi);
        int idx = (k >> 3) * 8 + (k & 3) * 2 + ((k >> 2) & 1);
        g_Ahi[base + idx] = hi;
        g_Alo[base + idx] = lo;
    }
}

// ---------------------------------------------------------------------------
// Kernel B2: transpose + tf32-split f_feats into frag-ordered g_Bhi/g_Blo.
// grid (16, 4, 128) (kblk32, fblk32, n), block (32, 8)
// ---------------------------------------------------------------------------
__global__ void split_b(const float* __restrict__ ff) {
    __shared__ float tbuf[32][33];
    int kbase = blockIdx.x * 32, fbase = blockIdx.y * 32, n = blockIdx.z;
    int tx = threadIdx.x, ty = threadIdx.y;
    const float* fin = ff + (size_t)n * F_ * D_;
#pragma unroll
    for (int i = 0; i < 4; i++) {
        tbuf[ty + i * 8][tx] = fin[(size_t)(fbase + ty + i * 8) * D_ + kbase + tx];
    }
    __syncthreads();
    size_t nb = (size_t)n * 65536;
#pragma unroll
    for (int i = 0; i < 4; i++) {
        int k = kbase + ty + i * 8;
        int f = fbase + tx;
        float x = tbuf[tx][ty + i * 8];
        float hi = to_tf32(x);
        float lo = to_tf32(x - hi);
        size_t idx = nb + (size_t)(k >> 3) * 1024 + (k & 3) * 256 + f * 2 + ((k >> 2) & 1);
        g_Bhi[idx] = hi;
        g_Blo[idx] = lo;
    }
}

// ---------------------------------------------------------------------------
__device__ __forceinline__ void cp_async16(char* sp, const float* gp) {
    unsigned sa = (unsigned)__cvta_generic_to_shared(sp);
    asm volatile("cp.async.cg.shared.global [%0], [%1], 16;\n" ::"r"(sa), "l"(gp));
}

__device__ __forceinline__ void mma_tf32(float* d, const uint32_t* a, const uint32_t* b) {
    asm("mma.sync.aligned.m16n8k8.row.col.f32.tf32.tf32.f32 "
        "{%0,%1,%2,%3}, {%4,%5,%6,%7}, {%8,%9}, {%0,%1,%2,%3};"
        : "+f"(d[0]), "+f"(d[1]), "+f"(d[2]), "+f"(d[3])
        : "r"(a[0]), "r"(a[1]), "r"(a[2]), "r"(a[3]), "r"(b[0]), "r"(b[1]));
}

// ---------------------------------------------------------------------------
// Kernel C: 3xTF32 HMMA GEMM + per-pair DTW.
// Grid (n=128, mblk=16), 256 threads = 8 warps. Warp w: rows (w&3)*32..+32,
// cols (w>>2)*64..+64 of the 128x128 S tile; DP warp w owns pair row-slab w.
//
// Smem (bytes), double buffered stages union'd with S:
//   stage buf b at b*37376:
//     AsH [128][20]f @ +0      (10240)
//     AsL [128][20]f @ +10240  (10240)
//     BsH [2][4][264]f @ +20480 (8448)
//     BsL @ +28928 (8448)
//   S[128][128]f @ 0 (after mainloop)
//   mvb @ 74752 (4096), rnf_s @ 78848 (64)
// ---------------------------------------------------------------------------
static constexpr int STG = 37376;
static constexpr int MVB_OFF = 74752;
static constexpr int RNF_OFF = 78848;
static constexpr int SMEM_TOTAL = 78912;

__global__ void __launch_bounds__(256, 2)
dtw_kernel(float* __restrict__ out) {
    extern __shared__ char smem[];
    float* Sf = (float*)smem;
    float* rnf_s = (float*)(smem + RNF_OFF);

    const int tid = threadIdx.x;
    const int wid = tid >> 5, lane = tid & 31;
    const int n = blockIdx.x, mblk = blockIdx.y;
    const int g = lane >> 2, t4 = lane & 3;
    const int R0 = (wid & 3) * 32, N0 = (wid >> 2) * 64;

    if (tid < 16) rnf_s[tid] = g_rnf[n * F_ + tid];

    const float* Ah = g_Ahi + (size_t)(mblk * 128) * 512;
    const float* Al = g_Alo + (size_t)(mblk * 128) * 512;
    const float* Bh = g_Bhi + (size_t)n * 65536;
    const float* Bl = g_Blo + (size_t)n * 65536;

    // stage tile kt (16 k) into buffer buf: 2048 16B chunks, 8 per thread
    auto stage = [&](int buf, int kt) {
        char* sb = smem + buf * STG;
#pragma unroll
        for (int i = 0; i < 8; i++) {
            int idx = tid + i * 256;
            if (idx < 1024) {
                int split = idx >> 9, rem = idx & 511;
                int r = rem >> 2, ch = rem & 3;
                const float* src = (split ? Al : Ah) + (size_t)r * 512 + kt * 16 + ch * 4;
                cp_async16(sb + (split ? 10240 : 0) + (r * 20 + ch * 4) * 4, src);
            } else {
                int idx2 = idx - 1024;
                int split = idx2 >> 9, rem = idx2 & 511;
                int r2 = rem >> 6, ch = rem & 63;
                const float* src = (split ? Bl : Bh) + kt * 2048 + r2 * 256 + ch * 4;
                cp_async16(sb + (split ? 28928 : 20480) + (r2 * 264 + ch * 4) * 4, src);
            }
        }
        asm volatile("cp.async.commit_group;\n" ::);
    };

    float acc[2][8][4];
#pragma unroll
    for (int mi = 0; mi < 2; mi++)
#pragma unroll
        for (int nb = 0; nb < 8; nb++)
#pragma unroll
            for (int d = 0; d < 4; d++) acc[mi][nb][d] = 0.0f;

    stage(0, 0);

    for (int kt = 0; kt < 32; kt++) {
        const int buf = kt & 1;
        if (kt + 1 < 32) {
            stage(buf ^ 1, kt + 1);
            asm volatile("cp.async.wait_group 1;\n" ::);
        } else {
            asm volatile("cp.async.wait_group 0;\n" ::);
        }
        __syncthreads();
        const char* sb = smem + buf * STG;
        const float* AsH = (const float*)sb;
        const float* AsL = AsH + 2560;
        const float* BsH = (const float*)(sb + 20480);
        const float* BsL = (const float*)(sb + 28928);
#pragma unroll
        for (int kblk = 0; kblk < 2; kblk++) {
            // A fragments (hi & lo): 2 m16 blocks x {a0,a2}/{a1,a3} via LDS.64
            uint32_t ah[2][4], al[2][4];
#pragma unroll
            for (int mi = 0; mi < 2; mi++) {
                int row = R0 + mi * 16 + g;
                float2 v0 = *(const float2*)&AsH[row * 20 + kblk * 8 + t4 * 2];
                float2 v1 = *(const float2*)&AsH[(row + 8) * 20 + kblk * 8 + t4 * 2];
                ah[mi][0] = __float_as_uint(v0.x); ah[mi][2] = __float_as_uint(v0.y);
                ah[mi][1] = __float_as_uint(v1.x); ah[mi][3] = __float_as_uint(v1.y);
                float2 w0 = *(const float2*)&AsL[row * 20 + kblk * 8 + t4 * 2];
                float2 w1 = *(const float2*)&AsL[(row + 8) * 20 + kblk * 8 + t4 * 2];
                al[mi][0] = __float_as_uint(w0.x); al[mi][2] = __float_as_uint(w0.y);
                al[mi][1] = __float_as_uint(w1.x); al[mi][3] = __float_as_uint(w1.y);
            }
#pragma unroll
            for (int nbh = 0; nbh < 2; nbh++) {
                uint32_t bh[4][2], bl[4][2];
#pragma unroll
                for (int q = 0; q < 4; q++) {
                    int nc = N0 + (nbh * 4 + q) * 8 + g;
                    float2 v = *(const float2*)&BsH[kblk * 1056 + t4 * 264 + nc * 2];
                    bh[q][0] = __float_as_uint(v.x); bh[q][1] = __float_as_uint(v.y);
                    float2 w = *(const float2*)&BsL[kblk * 1056 + t4 * 264 + nc * 2];
                    bl[q][0] = __float_as_uint(w.x); bl[q][1] = __float_as_uint(w.y);
                }
                // 3 passes: hi*hi, hi*lo, lo*hi (fp32 accumulate)
#pragma unroll
                for (int q = 0; q < 4; q++)
#pragma unroll
                    for (int mi = 0; mi < 2; mi++)
                        mma_tf32(acc[mi][nbh * 4 + q], ah[mi], bh[q]);
#pragma unroll
                for (int q = 0; q < 4; q++)
#pragma unroll
                    for (int mi = 0; mi < 2; mi++)
                        mma_tf32(acc[mi][nbh * 4 + q], ah[mi], bl[q]);
#pragma unroll
                for (int q = 0; q < 4; q++)
#pragma unroll
                    for (int mi = 0; mi < 2; mi++)
                        mma_tf32(acc[mi][nbh * 4 + q], al[mi], bh[q]);
            }
        }
        __syncthreads();
    }

    // Epilogue: fragment -> S with rescale (f<=c). d0,d1 = row, cols col,col+1;
    // d2,d3 = row+8.
#pragma unroll
    for (int mi = 0; mi < 2; mi++) {
#pragma unroll
        for (int nb = 0; nb < 8; nb++) {
            int row = R0 + mi * 16 + g;
            int col = N0 + nb * 8 + t4 * 2;
            float d0 = acc[mi][nb][0], d1 = acc[mi][nb][1];
            float d2 = acc[mi][nb][2], d3 = acc[mi][nb][3];
            int c0 = row & 15, c1 = (row + 8) & 15;
            if (col <= c0) d0 *= rnf_s[col];
            if (col + 1 <= c0) d1 *= rnf_s[col + 1];
            if (col <= c1) d2 *= rnf_s[col];
            if (col + 1 <= c1) d3 *= rnf_s[col + 1];
            float2 v0; v0.x = d0; v0.y = d1;
            float2 v1; v1.x = d2; v1.y = d3;
            *(float2*)&Sf[row * 128 + col] = v0;
            *(float2*)&Sf[(row + 8) * 128 + col] = v1;
        }
    }
    __syncthreads();  // S fully written (cross-warp) before DP

    // ---- DTW DP (reference's row-parallel form), one warp per pair ----
    const int w = wid;
    const float NEG = __int_as_float(0xff800000);  // -inf
    float Rp[4] = {NEG, NEG, NEG, NEG};
    float p_prev = 0.0f;
    float* Srows = Sf + w * 16 * 128;
    unsigned char* mvb = (unsigned char*)(smem + MVB_OFF) + w * 512;

    for (int i = 1; i <= 16; i++) {
        float4 sv = *(const float4*)&Srows[(i - 1) * 128 + lane * 4];
        float cl0 = sv.x, cl1 = cl0 + sv.y, cl2 = cl1 + sv.z, cl3 = cl2 + sv.w;
        float inc = cl3;
#pragma unroll
        for (int d = 1; d < 32; d <<= 1) {
            float tsh = __shfl_up_sync(0xffffffffu, inc, d);
            if (lane >= d) inc += tsh;
        }
        float ex = __shfl_up_sync(0xffffffffu, inc, 1);
        if (lane == 0) ex = 0.0f;
        float Cc0 = ex + cl0, Cc1 = ex + cl1, Cc2 = ex + cl2, Cc3 = ex + cl3;
        float rp_left = __shfl_up_sync(0xffffffffu, Rp[3], 1);
        if (lane == 0) rp_left = p_prev;
        float A0 = fmaxf(Rp[0], rp_left);
        float A1 = fmaxf(Rp[1], Rp[0]);
        float A2 = fmaxf(Rp[2], Rp[1]);
        float A3 = fmaxf(Rp[3], Rp[2]);
        float M0 = A0 - ex;
        float M1 = fmaxf(M0, A1 - Cc0);
        float M2 = fmaxf(M1, A2 - Cc1);
        float M3 = fmaxf(M2, A3 - Cc2);
        float mscan = M3;
#pragma unroll
        for (int d = 1; d < 32; d <<= 1) {
            float tsh = __shfl_up_sync(0xffffffffu, mscan, d);
            if (lane >= d) mscan = fmaxf(mscan, tsh);
        }
        float exm = __shfl_up_sync(0xffffffffu, mscan, 1);
        if (lane == 0) exm = NEG;
        float Rc[4];
        Rc[0] = Cc0 + fmaxf(M0, exm);
        Rc[1] = Cc1 + fmaxf(M1, exm);
        Rc[2] = Cc2 + fmaxf(M2, exm);
        Rc[3] = Cc3 + fmaxf(M3, exm);
        float rc_left = __shfl_up_sync(0xffffffffu, Rc[3], 1);
        if (lane == 0) rc_left = NEG;
        unsigned int byte = 0;
#pragma unroll
        for (int u = 0; u < 4; u++) {
            float up = Rp[u];
            float left = (u == 0) ? rc_left : Rc[u - 1];
            float dg = (u == 0) ? rp_left : Rp[u - 1];
            int m;
            if (up >= left && up >= dg) m = 0;
            else if (left >= dg) m = 1;
            else m = 2;
            byte |= (unsigned)m << (2 * u);
        }
        mvb[(i - 1) * 32 + lane] = (unsigned char)byte;
        Rp[0] = Rc[0]; Rp[1] = Rc[1]; Rp[2] = Rc[2]; Rp[3] = Rc[3];
        p_prev = NEG;
    }
    __syncwarp();

    // Zero mask (reuse S slab), then lane 0 backtracks writing 1.0
    float4* mreg = (float4*)Srows;
    for (int t2 = lane; t2 < 512; t2 += 32) mreg[t2] = make_float4(0.f, 0.f, 0.f, 0.f);
    __syncwarp();
    if (lane == 0) {
        int i = 16, j = 128;
        while (i > 0 && j > 0) {
            Srows[(i - 1) * 128 + (j - 1)] = 1.0f;
            unsigned int byte = mvb[(i - 1) * 32 + ((j - 1) >> 2)];
            int m = (byte >> (2 * ((j - 1) & 3))) & 3;
            if (m == 0) i -= 1;
            else if (m == 1) j -= 1;
            else { i -= 1; j -= 1; }
        }
    }
    __syncwarp();

    // Coalesced store: out[m][n][c][f]
    int mglob = mblk * 8 + w;
    float* outp = out + (((size_t)mglob * 128 + n) * 16) * 128;
    const float4* srcp = (const float4*)Srows;
    float4* dstp = (float4*)outp;
    for (int t2 = lane; t2 < 512; t2 += 32) dstp[t2] = srcp[t2];
}

// ---------------------------------------------------------------------------
extern "C" void kernel_launch(void* const* d_in, const int* in_sizes, int n_in,
                              void* d_out, int out_size) {
    const float* cf = (const float*)d_in[0];  // c_feats [128,16,512]
    const float* ff = (const float*)d_in[1];  // f_feats [128,128,512]
    float* out = (float*)d_out;               // [128,128,16,128] float32

    prep_norms<<<18432, 128>>>(cf, ff);
    split_a<<<2048, 128>>>(cf);
    {
        dim3 gsz(16, 4, 128), bsz(32, 8);
        split_b<<<gsz, bsz>>>(ff);
    }

    cudaFuncSetAttribute(dtw_kernel, cudaFuncAttributeMaxDynamicSharedMemorySize,
                         SMEM_TOTAL);
    dim3 grid(128, 16);
    dtw_kernel<<<grid, 256, SMEM_TOTAL>>>(out);
}

// round 15
// speedup vs baseline: 3.6710x; 3.6710x over previous
#include <cuda_runtime.h>
#include <cuda_fp16.h>
#include <cstdint>

// Problem dims (fixed)
#define D_ 512

// ---------------- global scratch (no allocation allowed) -------------------
// Fragment-linear fp16 operands (hi/lo split). 16B tuple per (block, kt, lane).
// A: [m16b=128][kt=32][lane=32][4 u32]  (2 MB each)
__device__ uint32_t g_Ah[128 * 32 * 32 * 4];
__device__ uint32_t g_Al[128 * 32 * 32 * 4];
// B: [n=128][qpair=8][kt=32][lane=32][4 u32]  (16 MB each)
__device__ uint32_t g_Bh[128 * 8 * 32 * 32 * 4];
__device__ uint32_t g_Bl[128 * 8 * 32 * 32 * 4];
__device__ float g_rnc[2048];              // 1/||c_feats row||
__device__ float g_rnf[128 * 128];         // 1/||f_feats[n,f]||

// ---------------------------------------------------------------------------
// Kernel A: reciprocal row norms for both tensors.
// ---------------------------------------------------------------------------
__global__ void prep_norms(const float* __restrict__ cf, const float* __restrict__ ff) {
    int row = blockIdx.x;
    int t = threadIdx.x;  // 128 threads, one float4 each
    const float* src = (row < 2048) ? (cf + (size_t)row * D_)
                                    : (ff + (size_t)(row - 2048) * D_);
    float4 v = ((const float4*)src)[t];
    float ss = v.x * v.x + v.y * v.y + v.z * v.z + v.w * v.w;
#pragma unroll
    for (int o = 16; o > 0; o >>= 1) ss += __shfl_xor_sync(0xffffffffu, ss, o);
    __shared__ float sred[4];
    if ((t & 31) == 0) sred[t >> 5] = ss;
    __syncthreads();
    if (t == 0) {
        float nrm = sqrtf(sred[0] + sred[1] + sred[2] + sred[3]);
        if (row < 2048) g_rnc[row] = 1.0f / nrm;
        else            g_rnf[row - 2048] = 1.0f / nrm;
    }
}

// hi/lo fp16 split, packed pair -> u32 (lo 16 bits = first elem)
__device__ __forceinline__ void split_pair(float x0, float x1, uint32_t& hi, uint32_t& lo) {
    __half h0 = __float2half_rn(x0), h1 = __float2half_rn(x1);
    __half l0 = __float2half_rn(x0 - __half2float(h0));
    __half l1 = __float2half_rn(x1 - __half2float(h1));
    hi = (uint32_t)__half_as_ushort(h0) | ((uint32_t)__half_as_ushort(h1) << 16);
    lo = (uint32_t)__half_as_ushort(l0) | ((uint32_t)__half_as_ushort(l1) << 16);
}

// ---------------------------------------------------------------------------
// Kernel A2: normalize + fp16-split c_feats into fragment tuples.
// Tuple (m16b, kt, lane=g*4+t4): a0={A[r][k0],A[r][k0+1]}, a1={A[r+8][k0],..},
// a2={A[r][k0+8],..}, a3={A[r+8][k0+8],..}; r=m16b*16+g, k0=kt*16+t4*2.
// grid (128, 4), block (32, 8)
// ---------------------------------------------------------------------------
__global__ void split_a(const float* __restrict__ cf) {
    int m16b = blockIdx.x;
    int kt = blockIdx.y * 8 + threadIdx.y;
    int lane = threadIdx.x;
    int g = lane >> 2, t4 = lane & 3;
    int r0 = m16b * 16 + g, r1 = r0 + 8;
    int k0 = kt * 16 + t4 * 2;
    float rn0 = g_rnc[r0], rn1 = g_rnc[r1];
    const float* p0 = cf + (size_t)r0 * D_ + k0;
    const float* p1 = cf + (size_t)r1 * D_ + k0;
    uint32_t hi[4], lo[4];
    split_pair(p0[0] * rn0, p0[1] * rn0, hi[0], lo[0]);
    split_pair(p1[0] * rn1, p1[1] * rn1, hi[1], lo[1]);
    split_pair(p0[8] * rn0, p0[9] * rn0, hi[2], lo[2]);
    split_pair(p1[8] * rn1, p1[9] * rn1, hi[3], lo[3]);
    size_t base = ((size_t)(m16b * 32 + kt) * 32 + lane) * 4;
    *(uint4*)&g_Ah[base] = make_uint4(hi[0], hi[1], hi[2], hi[3]);
    *(uint4*)&g_Al[base] = make_uint4(lo[0], lo[1], lo[2], lo[3]);
}

// ---------------------------------------------------------------------------
// Kernel B2: fp16-split f_feats into B fragment tuples (col = g).
// Tuple (n, qp, kt, lane): b0(q)={B[k0][f0],B[k0+1][f0]}, b1(q)={B[k0+8][f0],..},
// b0(q+1)/b1(q+1) with f1=f0+8; f0=qp*16+g, k0=kt*16+t4*2. B[k][f]=ff[n][f][k].
// grid (128, 32), block (32, 8)
// ---------------------------------------------------------------------------
__global__ void split_b(const float* __restrict__ ff) {
    int n = blockIdx.x, kt = blockIdx.y;
    int qp = threadIdx.y, lane = threadIdx.x;
    int g = lane >> 2, t4 = lane & 3;
    int f0 = qp * 16 + g, f1 = f0 + 8;
    int k0 = kt * 16 + t4 * 2;
    const float* fb = ff + (size_t)n * 128 * D_;
    const float* q0 = fb + (size_t)f0 * D_ + k0;
    const float* q1 = fb + (size_t)f1 * D_ + k0;
    uint32_t hi[4], lo[4];
    split_pair(q0[0], q0[1], hi[0], lo[0]);
    split_pair(q0[8], q0[9], hi[1], lo[1]);
    split_pair(q1[0], q1[1], hi[2], lo[2]);
    split_pair(q1[8], q1[9], hi[3], lo[3]);
    size_t base = (((size_t)(n * 8 + qp) * 32 + kt) * 32 + lane) * 4;
    *(uint4*)&g_Bh[base] = make_uint4(hi[0], hi[1], hi[2], hi[3]);
    *(uint4*)&g_Bl[base] = make_uint4(lo[0], lo[1], lo[2], lo[3]);
}

// ---------------------------------------------------------------------------
__device__ __forceinline__ void cp_async16(char* sp, const void* gp) {
    unsigned sa = (unsigned)__cvta_generic_to_shared(sp);
    asm volatile("cp.async.cg.shared.global [%0], [%1], 16;\n" ::"r"(sa), "l"(gp));
}

__device__ __forceinline__ void mma_f16(float* d, uint4 a, uint32_t b0, uint32_t b1) {
    asm("mma.sync.aligned.m16n8k16.row.col.f32.f16.f16.f32 "
        "{%0,%1,%2,%3}, {%4,%5,%6,%7}, {%8,%9}, {%0,%1,%2,%3};"
        : "+f"(d[0]), "+f"(d[1]), "+f"(d[2]), "+f"(d[3])
        : "r"(a.x), "r"(a.y), "r"(a.z), "r"(a.w), "r"(b0), "r"(b1));
}

// ---------------------------------------------------------------------------
// Kernel C: fp16x2 3-pass HMMA GEMM + per-pair DTW.
// Grid (n=128, mblk=16), 256 threads = 8 warps. Warp w: rows (w&3)*32..+32
// (m16 blocks (w&3)*2, +1), cols (w>>2)*64..+64 (qpairs (w>>2)*4..+4).
//
// Smem (bytes), double-buffered stages union'd with S:
//   stage buf b at b*16384: Ah 4K | Al 4K | Bh 4K | Bl 4K
//   S[128][128]f @ 0 (after mainloop), mvb @ 65536 (4K), rnf @ 69632
// ---------------------------------------------------------------------------
static constexpr int STG = 16384;
static constexpr int MVB_OFF = 65536;
static constexpr int RNF_OFF = 69632;
static constexpr int SMEM_TOTAL = 69760;

__global__ void __launch_bounds__(256, 2)
dtw_kernel(float* __restrict__ out) {
    extern __shared__ char smem[];
    float* Sf = (float*)smem;
    float* rnf_s = (float*)(smem + RNF_OFF);

    const int tid = threadIdx.x;
    const int wid = tid >> 5, lane = tid & 31;
    const int n = blockIdx.x, mblk = blockIdx.y;
    const int g = lane >> 2, t4 = lane & 3;
    const int R0 = (wid & 3) * 32, N0 = (wid >> 2) * 64;

    if (tid < 16) rnf_s[tid] = g_rnf[n * 128 + tid];

    // stage tile kt: 1024 16B tuples, 4 per thread (one per region)
    auto stage = [&](int buf, int kt) {
        char* sb = smem + buf * STG;
        const int loc = tid >> 5, ln = tid & 31;     // loc 0..7
        const int dst = (loc * 32 + ln) * 16;
        cp_async16(sb + dst,         &g_Ah[(((size_t)(mblk * 8 + loc) * 32 + kt) * 32 + ln) * 4]);
        cp_async16(sb + 4096 + dst,  &g_Al[(((size_t)(mblk * 8 + loc) * 32 + kt) * 32 + ln) * 4]);
        cp_async16(sb + 8192 + dst,  &g_Bh[(((size_t)(n * 8 + loc) * 32 + kt) * 32 + ln) * 4]);
        cp_async16(sb + 12288 + dst, &g_Bl[(((size_t)(n * 8 + loc) * 32 + kt) * 32 + ln) * 4]);
        asm volatile("cp.async.commit_group;\n" ::);
    };

    float acc[2][8][4];
#pragma unroll
    for (int mi = 0; mi < 2; mi++)
#pragma unroll
        for (int j = 0; j < 8; j++)
#pragma unroll
            for (int d = 0; d < 4; d++) acc[mi][j][d] = 0.0f;

    stage(0, 0);

    const int bi0 = (wid & 3) * 2, qp0 = (wid >> 2) * 4;
    for (int kt = 0; kt < 32; kt++) {
        const int buf = kt & 1;
        if (kt + 1 < 32) {
            stage(buf ^ 1, kt + 1);
            asm volatile("cp.async.wait_group 1;\n" ::);
        } else {
            asm volatile("cp.async.wait_group 0;\n" ::);
        }
        __syncthreads();
        const char* sb = smem + buf * STG;
        const uint32_t* Ah = (const uint32_t*)sb;
        const uint32_t* Al = (const uint32_t*)(sb + 4096);
        const uint32_t* Bh = (const uint32_t*)(sb + 8192);
        const uint32_t* Bl = (const uint32_t*)(sb + 12288);

        uint4 ah[2], al[2];
        ah[0] = *(const uint4*)&Ah[((bi0 + 0) * 32 + lane) * 4];
        ah[1] = *(const uint4*)&Ah[((bi0 + 1) * 32 + lane) * 4];
        al[0] = *(const uint4*)&Al[((bi0 + 0) * 32 + lane) * 4];
        al[1] = *(const uint4*)&Al[((bi0 + 1) * 32 + lane) * 4];
#pragma unroll
        for (int qq = 0; qq < 4; qq++) {
            uint4 bh = *(const uint4*)&Bh[((qp0 + qq) * 32 + lane) * 4];
            uint4 bl = *(const uint4*)&Bl[((qp0 + qq) * 32 + lane) * 4];
            // q even (cols qq*16 + 0..7): 3 passes x 2 mi
            mma_f16(acc[0][qq * 2], ah[0], bh.x, bh.y);
            mma_f16(acc[1][qq * 2], ah[1], bh.x, bh.y);
            mma_f16(acc[0][qq * 2], ah[0], bl.x, bl.y);
            mma_f16(acc[1][qq * 2], ah[1], bl.x, bl.y);
            mma_f16(acc[0][qq * 2], al[0], bh.x, bh.y);
            mma_f16(acc[1][qq * 2], al[1], bh.x, bh.y);
            // q odd (cols qq*16 + 8..15)
            mma_f16(acc[0][qq * 2 + 1], ah[0], bh.z, bh.w);
            mma_f16(acc[1][qq * 2 + 1], ah[1], bh.z, bh.w);
            mma_f16(acc[0][qq * 2 + 1], ah[0], bl.z, bl.w);
            mma_f16(acc[1][qq * 2 + 1], ah[1], bl.z, bl.w);
            mma_f16(acc[0][qq * 2 + 1], al[0], bh.z, bh.w);
            mma_f16(acc[1][qq * 2 + 1], al[1], bh.z, bh.w);
        }
        __syncthreads();
    }

    // Epilogue: fragments -> S with rescale (f<=c). c-frag: d0,d1 = (row, col..+1),
    // d2,d3 = (row+8, col..+1); row = R0+mi*16+g, col = N0+j*8+t4*2.
#pragma unroll
    for (int mi = 0; mi < 2; mi++) {
#pragma unroll
        for (int j = 0; j < 8; j++) {
            int row = R0 + mi * 16 + g;
            int col = N0 + j * 8 + t4 * 2;
            float d0 = acc[mi][j][0], d1 = acc[mi][j][1];
            float d2 = acc[mi][j][2], d3 = acc[mi][j][3];
            int c0 = row & 15, c1 = (row + 8) & 15;
            if (col <= c0) d0 *= rnf_s[col];
            if (col + 1 <= c0) d1 *= rnf_s[col + 1];
            if (col <= c1) d2 *= rnf_s[col];
            if (col + 1 <= c1) d3 *= rnf_s[col + 1];
            float2 v0; v0.x = d0; v0.y = d1;
            float2 v1; v1.x = d2; v1.y = d3;
            *(float2*)&Sf[row * 128 + col] = v0;
            *(float2*)&Sf[(row + 8) * 128 + col] = v1;
        }
    }
    __syncthreads();  // S fully written (cross-warp) before DP

    // ---- DTW DP (reference's row-parallel form), one warp per pair ----
    const int w = wid;
    const float NEG = __int_as_float(0xff800000);  // -inf
    float Rp[4] = {NEG, NEG, NEG, NEG};
    float p_prev = 0.0f;
    float* Srows = Sf + w * 16 * 128;
    unsigned char* mvb = (unsigned char*)(smem + MVB_OFF) + w * 512;

    for (int i = 1; i <= 16; i++) {
        float4 sv = *(const float4*)&Srows[(i - 1) * 128 + lane * 4];
        float cl0 = sv.x, cl1 = cl0 + sv.y, cl2 = cl1 + sv.z, cl3 = cl2 + sv.w;
        float inc = cl3;
#pragma unroll
        for (int d = 1; d < 32; d <<= 1) {
            float tsh = __shfl_up_sync(0xffffffffu, inc, d);
            if (lane >= d) inc += tsh;
        }
        float ex = __shfl_up_sync(0xffffffffu, inc, 1);
        if (lane == 0) ex = 0.0f;
        float Cc0 = ex + cl0, Cc1 = ex + cl1, Cc2 = ex + cl2, Cc3 = ex + cl3;
        float rp_left = __shfl_up_sync(0xffffffffu, Rp[3], 1);
        if (lane == 0) rp_left = p_prev;
        float A0 = fmaxf(Rp[0], rp_left);
        float A1 = fmaxf(Rp[1], Rp[0]);
        float A2 = fmaxf(Rp[2], Rp[1]);
        float A3 = fmaxf(Rp[3], Rp[2]);
        float M0 = A0 - ex;
        float M1 = fmaxf(M0, A1 - Cc0);
        float M2 = fmaxf(M1, A2 - Cc1);
        float M3 = fmaxf(M2, A3 - Cc2);
        float mscan = M3;
#pragma unroll
        for (int d = 1; d < 32; d <<= 1) {
            float tsh = __shfl_up_sync(0xffffffffu, mscan, d);
            if (lane >= d) mscan = fmaxf(mscan, tsh);
        }
        float exm = __shfl_up_sync(0xffffffffu, mscan, 1);
        if (lane == 0) exm = NEG;
        float Rc[4];
        Rc[0] = Cc0 + fmaxf(M0, exm);
        Rc[1] = Cc1 + fmaxf(M1, exm);
        Rc[2] = Cc2 + fmaxf(M2, exm);
        Rc[3] = Cc3 + fmaxf(M3, exm);
        float rc_left = __shfl_up_sync(0xffffffffu, Rc[3], 1);
        if (lane == 0) rc_left = NEG;
        unsigned int byte = 0;
#pragma unroll
        for (int u = 0; u < 4; u++) {
            float up = Rp[u];
            float left = (u == 0) ? rc_left : Rc[u - 1];
            float dg = (u == 0) ? rp_left : Rp[u - 1];
            int m;
            if (up >= left && up >= dg) m = 0;
            else if (left >= dg) m = 1;
            else m = 2;
            byte |= (unsigned)m << (2 * u);
        }
        mvb[(i - 1) * 32 + lane] = (unsigned char)byte;
        Rp[0] = Rc[0]; Rp[1] = Rc[1]; Rp[2] = Rc[2]; Rp[3] = Rc[3];
        p_prev = NEG;
    }
    __syncwarp();

    // Zero mask (reuse S slab), then lane 0 backtracks writing 1.0
    float4* mreg = (float4*)Srows;
    for (int t2 = lane; t2 < 512; t2 += 32) mreg[t2] = make_float4(0.f, 0.f, 0.f, 0.f);
    __syncwarp();
    if (lane == 0) {
        int i = 16, j = 128;
        while (i > 0 && j > 0) {
            Srows[(i - 1) * 128 + (j - 1)] = 1.0f;
            unsigned int byte = mvb[(i - 1) * 32 + ((j - 1) >> 2)];
            int m = (byte >> (2 * ((j - 1) & 3))) & 3;
            if (m == 0) i -= 1;
            else if (m == 1) j -= 1;
            else { i -= 1; j -= 1; }
        }
    }
    __syncwarp();

    // Coalesced store: out[m][n][c][f]
    int mglob = mblk * 8 + w;
    float* outp = out + (((size_t)mglob * 128 + n) * 16) * 128;
    const float4* srcp = (const float4*)Srows;
    float4* dstp = (float4*)outp;
    for (int t2 = lane; t2 < 512; t2 += 32) dstp[t2] = srcp[t2];
}

// ---------------------------------------------------------------------------
extern "C" void kernel_launch(void* const* d_in, const int* in_sizes, int n_in,
                              void* d_out, int out_size) {
    const float* cf = (const float*)d_in[0];  // c_feats [128,16,512]
    const float* ff = (const float*)d_in[1];  // f_feats [128,128,512]
    float* out = (float*)d_out;               // [128,128,16,128] float32

    prep_norms<<<18432, 128>>>(cf, ff);
    {
        dim3 g(128, 4), b(32, 8);
        split_a<<<g, b>>>(cf);
    }
    {
        dim3 g(128, 32), b(32, 8);
        split_b<<<g, b>>>(ff);
    }

    cudaFuncSetAttribute(dtw_kernel, cudaFuncAttributeMaxDynamicSharedMemorySize,
                         SMEM_TOTAL);
    dim3 grid(128, 16);
    dtw_kernel<<<grid, 256, SMEM_TOTAL>>>(out);
}